// round 2
// baseline (speedup 1.0000x reference)
#include <cuda_runtime.h>
#include <cuda_bf16.h>

#define NN 100000
#define EE 1600000
#define DIN 128
#define DHID 64
#define DOUT 32

// Scratch (allocation-free contract: __device__ globals)
__device__ float g_deg[NN];
__device__ float g_isq[NN];       // deg^{-1/2}
__device__ float g_idg[NN];       // deg^{-1}  (self-loop norm)
__device__ float g_norm[EE];      // per-edge norm, reused by both layers
__device__ float g_h1[NN * DHID]; // x @ W1
__device__ float g_a1[NN * DHID]; // aggregated layer-1 (pre relu/bias)
__device__ float g_h3[NN * DOUT]; // relu(a1+b1) @ W2

// ---------------------------------------------------------------- degree/norm
__global__ void k_deg_init(int n) {
    int i = blockIdx.x * blockDim.x + threadIdx.x;
    if (i < n) g_deg[i] = 1.0f;  // self-loop
}

__global__ void k_deg_count(const int* __restrict__ dst, int e) {
    int i = blockIdx.x * blockDim.x + threadIdx.x;
    if (i < e) atomicAdd(&g_deg[dst[i]], 1.0f);
}

__global__ void k_deg_fin(int n) {
    int i = blockIdx.x * blockDim.x + threadIdx.x;
    if (i < n) {
        float d = g_deg[i];
        g_isq[i] = rsqrtf(d);
        g_idg[i] = 1.0f / d;
    }
}

__global__ void k_norm(const int* __restrict__ src, const int* __restrict__ dst, int e) {
    int i = blockIdx.x * blockDim.x + threadIdx.x;
    if (i < e) g_norm[i] = g_isq[src[i]] * g_isq[dst[i]];
}

// ---------------------------------------------------------------- GEMM1: h1 = x @ W1  [N,128]x[128,64]
// Block: 64 rows x 64 cols, 256 threads, each thread 4x4 outputs.
__global__ __launch_bounds__(256) void k_gemm1(const float* __restrict__ x,
                                               const float* __restrict__ W, int n) {
    __shared__ float Xs[64][DIN];  // 32 KB
    int tid = threadIdx.x;
    int rb = blockIdx.x * 64;
    int rows = n - rb; if (rows > 64) rows = 64;

    const float4* x4 = (const float4*)(x + (size_t)rb * DIN);
    float4* Xs4 = (float4*)Xs;
    for (int i = tid; i < rows * (DIN / 4); i += 256) Xs4[i] = x4[i];
    __syncthreads();

    int colq = tid & 15;  // cols 4*colq .. +3
    int rowq = tid >> 4;  // rows 4*rowq .. +3
    float acc[4][4] = {};
    const float4* W4 = (const float4*)W;  // row k = 16 float4s

#pragma unroll 8
    for (int k = 0; k < DIN; k += 4) {
        float4 xr[4];
#pragma unroll
        for (int i = 0; i < 4; i++)
            xr[i] = *(const float4*)&Xs[rowq * 4 + i][k];
#pragma unroll
        for (int kk = 0; kk < 4; kk++) {
            float4 w = __ldg(&W4[(k + kk) * 16 + colq]);
#pragma unroll
            for (int i = 0; i < 4; i++) {
                float xv = ((const float*)&xr[i])[kk];
                acc[i][0] = fmaf(xv, w.x, acc[i][0]);
                acc[i][1] = fmaf(xv, w.y, acc[i][1]);
                acc[i][2] = fmaf(xv, w.z, acc[i][2]);
                acc[i][3] = fmaf(xv, w.w, acc[i][3]);
            }
        }
    }
#pragma unroll
    for (int i = 0; i < 4; i++) {
        int r = rb + rowq * 4 + i;
        if (r < n) {
            float4 v = make_float4(acc[i][0], acc[i][1], acc[i][2], acc[i][3]);
            *(float4*)&g_h1[(size_t)r * DHID + colq * 4] = v;
        }
    }
}

// ---------------------------------------------------------------- self-loop init layer1: a1[i] = h1[i]/deg[i]
__global__ void k_selfinit1(int n) {
    int i = blockIdx.x * blockDim.x + threadIdx.x;  // over n*16 float4s
    if (i < n * 16) {
        float4 v = ((const float4*)g_h1)[i];
        float s = g_idg[i >> 4];
        v.x *= s; v.y *= s; v.z *= s; v.w *= s;
        ((float4*)g_a1)[i] = v;
    }
}

// ---------------------------------------------------------------- scatter layer1: 16 threads/edge, float4 atomics
__global__ void k_scatter1(const int* __restrict__ src, const int* __restrict__ dst, int e) {
    long long t = (long long)blockIdx.x * blockDim.x + threadIdx.x;
    if (t >= (long long)e * 16) return;
    int ed = (int)(t >> 4);
    int q  = (int)(t & 15);
    float nm = g_norm[ed];
    int s = src[ed], d = dst[ed];
    float4 v = ((const float4*)g_h1)[s * 16 + q];
    v.x *= nm; v.y *= nm; v.z *= nm; v.w *= nm;
#if defined(__CUDA_ARCH__) && __CUDA_ARCH__ >= 900
    atomicAdd((float4*)&g_a1[(size_t)d * DHID + q * 4], v);
#else
    float* p = &g_a1[(size_t)d * DHID + q * 4];
    atomicAdd(p + 0, v.x); atomicAdd(p + 1, v.y);
    atomicAdd(p + 2, v.z); atomicAdd(p + 3, v.w);
#endif
}

// ---------------------------------------------------------------- GEMM2: h3 = relu(a1+b1) @ W2  [N,64]x[64,32]
// Block: 64 rows x 32 cols, 256 threads, each thread 2x4 outputs. ReLU+bias fused into A load.
__global__ __launch_bounds__(256) void k_gemm2(const float* __restrict__ W,
                                               const float* __restrict__ b1, int n) {
    __shared__ float Xs[64][DHID];  // 16 KB
    int tid = threadIdx.x;
    int rb = blockIdx.x * 64;
    int rows = n - rb; if (rows > 64) rows = 64;

    const float4* a4 = (const float4*)g_a1 + (size_t)rb * (DHID / 4);
    float4* Xs4 = (float4*)Xs;
    const float4* b4 = (const float4*)b1;
    for (int i = tid; i < rows * (DHID / 4); i += 256) {
        float4 v = a4[i];
        float4 b = __ldg(&b4[i & 15]);
        v.x = fmaxf(v.x + b.x, 0.0f);
        v.y = fmaxf(v.y + b.y, 0.0f);
        v.z = fmaxf(v.z + b.z, 0.0f);
        v.w = fmaxf(v.w + b.w, 0.0f);
        Xs4[i] = v;
    }
    __syncthreads();

    int colq = tid & 7;   // cols 4*colq .. +3  (32 cols)
    int rowq = tid >> 3;  // rows 2*rowq .. +1  (64 rows)
    float acc[2][4] = {};
    const float4* W4 = (const float4*)W;  // row k = 8 float4s

#pragma unroll 8
    for (int k = 0; k < DHID; k += 4) {
        float4 xr[2];
#pragma unroll
        for (int i = 0; i < 2; i++)
            xr[i] = *(const float4*)&Xs[rowq * 2 + i][k];
#pragma unroll
        for (int kk = 0; kk < 4; kk++) {
            float4 w = __ldg(&W4[(k + kk) * 8 + colq]);
#pragma unroll
            for (int i = 0; i < 2; i++) {
                float xv = ((const float*)&xr[i])[kk];
                acc[i][0] = fmaf(xv, w.x, acc[i][0]);
                acc[i][1] = fmaf(xv, w.y, acc[i][1]);
                acc[i][2] = fmaf(xv, w.z, acc[i][2]);
                acc[i][3] = fmaf(xv, w.w, acc[i][3]);
            }
        }
    }
#pragma unroll
    for (int i = 0; i < 2; i++) {
        int r = rb + rowq * 2 + i;
        if (r < n) {
            float4 v = make_float4(acc[i][0], acc[i][1], acc[i][2], acc[i][3]);
            *(float4*)&g_h3[(size_t)r * DOUT + colq * 4] = v;
        }
    }
}

// ---------------------------------------------------------------- self-loop init layer2: out[i] = h3[i]/deg[i] + b2
__global__ void k_selfinit2(const float* __restrict__ b2, float* __restrict__ out, int n) {
    int i = blockIdx.x * blockDim.x + threadIdx.x;  // over n*8 float4s
    if (i < n * 8) {
        float4 v = ((const float4*)g_h3)[i];
        float s = g_idg[i >> 3];
        float4 b = __ldg(&((const float4*)b2)[i & 7]);
        v.x = fmaf(v.x, s, b.x);
        v.y = fmaf(v.y, s, b.y);
        v.z = fmaf(v.z, s, b.z);
        v.w = fmaf(v.w, s, b.w);
        ((float4*)out)[i] = v;
    }
}

// ---------------------------------------------------------------- scatter layer2: 8 threads/edge
__global__ void k_scatter2(const int* __restrict__ src, const int* __restrict__ dst,
                           float* __restrict__ out, int e) {
    long long t = (long long)blockIdx.x * blockDim.x + threadIdx.x;
    if (t >= (long long)e * 8) return;
    int ed = (int)(t >> 3);
    int q  = (int)(t & 7);
    float nm = g_norm[ed];
    int s = src[ed], d = dst[ed];
    float4 v = ((const float4*)g_h3)[s * 8 + q];
    v.x *= nm; v.y *= nm; v.z *= nm; v.w *= nm;
#if defined(__CUDA_ARCH__) && __CUDA_ARCH__ >= 900
    atomicAdd((float4*)&out[(size_t)d * DOUT + q * 4], v);
#else
    float* p = &out[(size_t)d * DOUT + q * 4];
    atomicAdd(p + 0, v.x); atomicAdd(p + 1, v.y);
    atomicAdd(p + 2, v.z); atomicAdd(p + 3, v.w);
#endif
}

// ----------------------------------------------------------------
extern "C" void kernel_launch(void* const* d_in, const int* in_sizes, int n_in,
                              void* d_out, int out_size) {
    const float* x  = (const float*)d_in[0];
    const int*   ei = (const int*)d_in[1];
    const float* W1 = (const float*)d_in[2];
    const float* b1 = (const float*)d_in[3];
    const float* W2 = (const float*)d_in[4];
    const float* b2 = (const float*)d_in[5];
    float* out = (float*)d_out;

    int n = in_sizes[0] / DIN;
    int e = in_sizes[1] / 2;
    const int* src = ei;
    const int* dst = ei + e;

    k_deg_init<<<(n + 255) / 256, 256>>>(n);
    k_deg_count<<<(e + 255) / 256, 256>>>(dst, e);
    k_deg_fin<<<(n + 255) / 256, 256>>>(n);
    k_norm<<<(e + 255) / 256, 256>>>(src, dst, e);

    k_gemm1<<<(n + 63) / 64, 256>>>(x, W1, n);
    k_selfinit1<<<(n * 16 + 255) / 256, 256>>>(n);
    {
        long long tot = (long long)e * 16;
        k_scatter1<<<(unsigned)((tot + 255) / 256), 256>>>(src, dst, e);
    }

    k_gemm2<<<(n + 63) / 64, 256>>>(W2, b1, n);
    k_selfinit2<<<(n * 8 + 255) / 256, 256>>>(b2, out, n);
    {
        long long tot = (long long)e * 8;
        k_scatter2<<<(unsigned)((tot + 255) / 256), 256>>>(src, dst, out, e);
    }
}

// round 3
// speedup vs baseline: 1.3000x; 1.3000x over previous
#include <cuda_runtime.h>
#include <cuda_bf16.h>

#define NN 100000
#define EE 1600000
#define DIN 128
#define DHID 64
#define DOUT 32
#define SCAN_BLK 1024
#define MAX_SBLK 128

// Scratch (allocation-free contract: __device__ globals)
__device__ int   g_cnt[NN];        // edge count per dst (excl. self-loop)
__device__ int   g_offs[NN];       // CSR exclusive offsets
__device__ int   g_cursor[NN];     // fill cursors
__device__ int   g_bsum[MAX_SBLK]; // scan block sums
__device__ int   g_bpre[MAX_SBLK]; // scan block prefixes
__device__ float g_isq[NN];        // (deg+1)^{-1/2}
__device__ int   g_csrc[EE];       // CSR-sorted source indices
__device__ float g_h1[NN * DHID];  // x @ W1
__device__ float g_a1[NN * DHID];  // aggregated layer-1 (pre relu/bias)
__device__ float g_h3[NN * DOUT];  // relu(a1+b1) @ W2

// ---------------------------------------------------------------- CSR build
__global__ void k_zero(int n) {
    int i = blockIdx.x * blockDim.x + threadIdx.x;
    if (i < n) g_cnt[i] = 0;
}

__global__ void k_count(const int* __restrict__ dst, int e) {
    int i = blockIdx.x * blockDim.x + threadIdx.x;
    if (i < e) atomicAdd(&g_cnt[dst[i]], 1);
}

// pass 1: per-block inclusive scan of g_cnt, write exclusive prefix + block sums
__global__ __launch_bounds__(SCAN_BLK) void k_scan1(int n) {
    __shared__ int s[SCAN_BLK];
    int i = blockIdx.x * SCAN_BLK + threadIdx.x;
    int v = (i < n) ? g_cnt[i] : 0;
    s[threadIdx.x] = v;
    __syncthreads();
    for (int d = 1; d < SCAN_BLK; d <<= 1) {
        int t = (threadIdx.x >= d) ? s[threadIdx.x - d] : 0;
        __syncthreads();
        s[threadIdx.x] += t;
        __syncthreads();
    }
    if (i < n) g_offs[i] = s[threadIdx.x] - v;  // exclusive within block
    if (threadIdx.x == SCAN_BLK - 1) g_bsum[blockIdx.x] = s[SCAN_BLK - 1];
}

// pass 2: single-block scan of block sums
__global__ __launch_bounds__(MAX_SBLK) void k_scan2(int nb) {
    __shared__ int s[MAX_SBLK];
    int v = (threadIdx.x < nb) ? g_bsum[threadIdx.x] : 0;
    s[threadIdx.x] = v;
    __syncthreads();
    for (int d = 1; d < MAX_SBLK; d <<= 1) {
        int t = (threadIdx.x >= d) ? s[threadIdx.x - d] : 0;
        __syncthreads();
        s[threadIdx.x] += t;
        __syncthreads();
    }
    if (threadIdx.x < nb) g_bpre[threadIdx.x] = s[threadIdx.x] - v;
}

// pass 3: finalize offsets + cursors + degree normalizers
__global__ void k_scan3_fin(int n) {
    int i = blockIdx.x * blockDim.x + threadIdx.x;
    if (i < n) {
        int off = g_offs[i] + g_bpre[i >> 10];  // SCAN_BLK == 1024
        g_offs[i] = off;
        g_cursor[i] = off;
        g_isq[i] = rsqrtf((float)(g_cnt[i] + 1));  // +1 self-loop
    }
}

__global__ void k_fill(const int* __restrict__ src, const int* __restrict__ dst, int e) {
    int i = blockIdx.x * blockDim.x + threadIdx.x;
    if (i < e) {
        int p = atomicAdd(&g_cursor[dst[i]], 1);
        g_csrc[p] = src[i];
    }
}

// ---------------------------------------------------------------- GEMM1: h1 = x @ W1  [N,128]x[128,64]
__global__ __launch_bounds__(256) void k_gemm1(const float* __restrict__ x,
                                               const float* __restrict__ W, int n) {
    __shared__ float Xs[64][DIN];  // 32 KB
    int tid = threadIdx.x;
    int rb = blockIdx.x * 64;
    int rows = n - rb; if (rows > 64) rows = 64;

    const float4* x4 = (const float4*)(x + (size_t)rb * DIN);
    float4* Xs4 = (float4*)Xs;
    for (int i = tid; i < rows * (DIN / 4); i += 256) Xs4[i] = x4[i];
    __syncthreads();

    int colq = tid & 15;
    int rowq = tid >> 4;
    float acc[4][4] = {};
    const float4* W4 = (const float4*)W;

#pragma unroll 8
    for (int k = 0; k < DIN; k += 4) {
        float4 xr[4];
#pragma unroll
        for (int i = 0; i < 4; i++)
            xr[i] = *(const float4*)&Xs[rowq * 4 + i][k];
#pragma unroll
        for (int kk = 0; kk < 4; kk++) {
            float4 w = __ldg(&W4[(k + kk) * 16 + colq]);
#pragma unroll
            for (int i = 0; i < 4; i++) {
                float xv = ((const float*)&xr[i])[kk];
                acc[i][0] = fmaf(xv, w.x, acc[i][0]);
                acc[i][1] = fmaf(xv, w.y, acc[i][1]);
                acc[i][2] = fmaf(xv, w.z, acc[i][2]);
                acc[i][3] = fmaf(xv, w.w, acc[i][3]);
            }
        }
    }
#pragma unroll
    for (int i = 0; i < 4; i++) {
        int r = rb + rowq * 4 + i;
        if (r < n) {
            float4 v = make_float4(acc[i][0], acc[i][1], acc[i][2], acc[i][3]);
            *(float4*)&g_h1[(size_t)r * DHID + colq * 4] = v;
        }
    }
}

// ---------------------------------------------------------------- agg1: warp per dst node, 64 dims (float2/lane)
// a1[d] = isq[d] * ( isq[d]*h1[d] + sum_{s in N(d)} isq[s]*h1[s] )
__global__ __launch_bounds__(256) void k_agg1(int n) {
    int w = (blockIdx.x * 256 + threadIdx.x) >> 5;
    int lane = threadIdx.x & 31;
    if (w >= n) return;
    int beg = g_offs[w];
    int end = beg + g_cnt[w];
    float isqd = g_isq[w];
    const float2* h = (const float2*)g_h1;

    float2 self = h[(size_t)w * 32 + lane];
    float2 acc;
    acc.x = isqd * self.x;
    acc.y = isqd * self.y;

    int j = beg;
    for (; j + 1 < end; j += 2) {
        int s0 = g_csrc[j], s1 = g_csrc[j + 1];
        float w0 = g_isq[s0], w1 = g_isq[s1];
        float2 v0 = h[(size_t)s0 * 32 + lane];
        float2 v1 = h[(size_t)s1 * 32 + lane];
        acc.x = fmaf(w0, v0.x, acc.x);
        acc.y = fmaf(w0, v0.y, acc.y);
        acc.x = fmaf(w1, v1.x, acc.x);
        acc.y = fmaf(w1, v1.y, acc.y);
    }
    if (j < end) {
        int s0 = g_csrc[j];
        float w0 = g_isq[s0];
        float2 v0 = h[(size_t)s0 * 32 + lane];
        acc.x = fmaf(w0, v0.x, acc.x);
        acc.y = fmaf(w0, v0.y, acc.y);
    }
    acc.x *= isqd;
    acc.y *= isqd;
    ((float2*)g_a1)[(size_t)w * 32 + lane] = acc;
}

// ---------------------------------------------------------------- GEMM2: h3 = relu(a1+b1) @ W2  [N,64]x[64,32]
__global__ __launch_bounds__(256) void k_gemm2(const float* __restrict__ W,
                                               const float* __restrict__ b1, int n) {
    __shared__ float Xs[64][DHID];  // 16 KB
    int tid = threadIdx.x;
    int rb = blockIdx.x * 64;
    int rows = n - rb; if (rows > 64) rows = 64;

    const float4* a4 = (const float4*)g_a1 + (size_t)rb * (DHID / 4);
    float4* Xs4 = (float4*)Xs;
    const float4* b4 = (const float4*)b1;
    for (int i = tid; i < rows * (DHID / 4); i += 256) {
        float4 v = a4[i];
        float4 b = __ldg(&b4[i & 15]);
        v.x = fmaxf(v.x + b.x, 0.0f);
        v.y = fmaxf(v.y + b.y, 0.0f);
        v.z = fmaxf(v.z + b.z, 0.0f);
        v.w = fmaxf(v.w + b.w, 0.0f);
        Xs4[i] = v;
    }
    __syncthreads();

    int colq = tid & 7;
    int rowq = tid >> 3;
    float acc[2][4] = {};
    const float4* W4 = (const float4*)W;

#pragma unroll 8
    for (int k = 0; k < DHID; k += 4) {
        float4 xr[2];
#pragma unroll
        for (int i = 0; i < 2; i++)
            xr[i] = *(const float4*)&Xs[rowq * 2 + i][k];
#pragma unroll
        for (int kk = 0; kk < 4; kk++) {
            float4 w = __ldg(&W4[(k + kk) * 8 + colq]);
#pragma unroll
            for (int i = 0; i < 2; i++) {
                float xv = ((const float*)&xr[i])[kk];
                acc[i][0] = fmaf(xv, w.x, acc[i][0]);
                acc[i][1] = fmaf(xv, w.y, acc[i][1]);
                acc[i][2] = fmaf(xv, w.z, acc[i][2]);
                acc[i][3] = fmaf(xv, w.w, acc[i][3]);
            }
        }
    }
#pragma unroll
    for (int i = 0; i < 2; i++) {
        int r = rb + rowq * 2 + i;
        if (r < n) {
            float4 v = make_float4(acc[i][0], acc[i][1], acc[i][2], acc[i][3]);
            *(float4*)&g_h3[(size_t)r * DOUT + colq * 4] = v;
        }
    }
}

// ---------------------------------------------------------------- agg2: warp per dst node, 32 dims (float/lane)
// out[d] = isq[d] * ( isq[d]*h3[d] + sum isq[s]*h3[s] ) + b2
__global__ __launch_bounds__(256) void k_agg2(float* __restrict__ out,
                                              const float* __restrict__ b2, int n) {
    int w = (blockIdx.x * 256 + threadIdx.x) >> 5;
    int lane = threadIdx.x & 31;
    if (w >= n) return;
    int beg = g_offs[w];
    int end = beg + g_cnt[w];
    float isqd = g_isq[w];

    float acc = isqd * g_h3[(size_t)w * 32 + lane];

    int j = beg;
    for (; j + 1 < end; j += 2) {
        int s0 = g_csrc[j], s1 = g_csrc[j + 1];
        float w0 = g_isq[s0], w1 = g_isq[s1];
        float v0 = g_h3[(size_t)s0 * 32 + lane];
        float v1 = g_h3[(size_t)s1 * 32 + lane];
        acc = fmaf(w0, v0, acc);
        acc = fmaf(w1, v1, acc);
    }
    if (j < end) {
        int s0 = g_csrc[j];
        acc = fmaf(g_isq[s0], g_h3[(size_t)s0 * 32 + lane], acc);
    }
    out[(size_t)w * 32 + lane] = fmaf(acc, isqd, __ldg(&b2[lane]));
}

// ----------------------------------------------------------------
extern "C" void kernel_launch(void* const* d_in, const int* in_sizes, int n_in,
                              void* d_out, int out_size) {
    const float* x  = (const float*)d_in[0];
    const int*   ei = (const int*)d_in[1];
    const float* W1 = (const float*)d_in[2];
    const float* b1 = (const float*)d_in[3];
    const float* W2 = (const float*)d_in[4];
    const float* b2 = (const float*)d_in[5];
    float* out = (float*)d_out;

    int n = in_sizes[0] / DIN;
    int e = in_sizes[1] / 2;
    const int* src = ei;
    const int* dst = ei + e;
    int nsb = (n + SCAN_BLK - 1) / SCAN_BLK;  // scan blocks (<=128)

    // CSR build
    k_zero<<<(n + 255) / 256, 256>>>(n);
    k_count<<<(e + 255) / 256, 256>>>(dst, e);
    k_scan1<<<nsb, SCAN_BLK>>>(n);
    k_scan2<<<1, MAX_SBLK>>>(nsb);
    k_scan3_fin<<<(n + 255) / 256, 256>>>(n);
    k_fill<<<(e + 255) / 256, 256>>>(src, dst, e);

    // Layer 1
    k_gemm1<<<(n + 63) / 64, 256>>>(x, W1, n);
    k_agg1<<<(n * 32 + 255) / 256, 256>>>(n);

    // Layer 2
    k_gemm2<<<(n + 63) / 64, 256>>>(W2, b1, n);
    k_agg2<<<(n * 32 + 255) / 256, 256>>>(out, b2, n);
}

// round 4
// speedup vs baseline: 1.3538x; 1.0413x over previous
#include <cuda_runtime.h>
#include <cuda_bf16.h>

#define NN 100000
#define EE 1600000
#define DIN 128
#define DHID 64
#define DOUT 32
#define SCAN_BLK 1024

// Scratch (allocation-free contract: __device__ globals)
__device__ int   g_cnt[NN];        // edge count per dst (excl. self-loop)
__device__ int   g_offs[NN];       // CSR offsets (segment order nondeterministic, contents valid)
__device__ int   g_cursor[NN];     // fill cursors
__device__ int   g_etotal;         // global edge-slot counter
__device__ float g_isq[NN];        // (deg+1)^{-1/2}
__device__ int   g_csrc[EE];       // CSR-sorted source indices
__device__ float g_h1[NN * DHID];  // x @ W1
__device__ float g_a1[NN * DHID];  // aggregated layer-1 (pre relu/bias)
__device__ float g_h3[NN * DOUT];  // relu(a1+b1) @ W2

// ---------------------------------------------------------------- CSR build
__global__ void k_zero(int n) {
    int i = blockIdx.x * blockDim.x + threadIdx.x;
    if (i < n) g_cnt[i] = 0;
    if (i == 0) g_etotal = 0;
}

__global__ void k_count(const int* __restrict__ dst, int e) {
    int i = blockIdx.x * blockDim.x + threadIdx.x;
    if (i < e) atomicAdd(&g_cnt[dst[i]], 1);
}

// single-pass: block scan + atomic block base (CSR segments in arbitrary block order)
__global__ __launch_bounds__(SCAN_BLK) void k_offsets(int n) {
    __shared__ int s[SCAN_BLK];
    __shared__ int base;
    int i = blockIdx.x * SCAN_BLK + threadIdx.x;
    int c = (i < n) ? g_cnt[i] : 0;
    s[threadIdx.x] = c;
    __syncthreads();
    for (int d = 1; d < SCAN_BLK; d <<= 1) {
        int t = (threadIdx.x >= d) ? s[threadIdx.x - d] : 0;
        __syncthreads();
        s[threadIdx.x] += t;
        __syncthreads();
    }
    if (threadIdx.x == SCAN_BLK - 1) base = atomicAdd(&g_etotal, s[SCAN_BLK - 1]);
    __syncthreads();
    if (i < n) {
        int off = base + s[threadIdx.x] - c;
        g_offs[i] = off;
        g_cursor[i] = off;
        g_isq[i] = rsqrtf((float)(c + 1));  // +1 self-loop
    }
}

__global__ void k_fill(const int* __restrict__ src, const int* __restrict__ dst, int e) {
    int i = blockIdx.x * blockDim.x + threadIdx.x;
    if (i < e) {
        int p = atomicAdd(&g_cursor[dst[i]], 1);
        g_csrc[p] = src[i];
    }
}

// ---------------------------------------------------------------- GEMM1 (TF32 tensor): h1 = x @ W1
// Block: 128 rows x 64 cols, 256 threads (8 warps), warp w -> rows [16w,16w+16), all 64 cols.
// mma.sync.aligned.m16n8k8.row.col.f32.tf32.tf32.f32, 16 k-steps.
#define XS_STRIDE 132  // pad: bank = (4*row + col) % 32, conflict-free frag loads

__device__ __forceinline__ unsigned f2tf32(float f) {
    unsigned r;
    asm("cvt.rna.tf32.f32 %0, %1;" : "=r"(r) : "f"(f));
    return r;
}

__global__ __launch_bounds__(256) void k_gemm1_tf32(const float* __restrict__ x,
                                                    const float* __restrict__ W, int n) {
    extern __shared__ float Xs[];  // [128][XS_STRIDE]
    int tid = threadIdx.x;
    int warp = tid >> 5;
    int lane = tid & 31;
    int gid = lane >> 2;   // groupID 0..7
    int tig = lane & 3;    // thread-in-group 0..3
    int rb = blockIdx.x * 128;

    // stage X tile [128 x 128] as float4, zero-fill OOB rows
    {
        float4* Xs4 = (float4*)Xs;
        const float4 zz = make_float4(0.f, 0.f, 0.f, 0.f);
        for (int idx = tid; idx < 128 * 32; idx += 256) {
            int row = idx >> 5, c4 = idx & 31;
            float4 v = (rb + row < n)
                     ? __ldg((const float4*)(x + (size_t)(rb + row) * DIN) + c4)
                     : zz;
            Xs4[row * (XS_STRIDE / 4) + c4] = v;
        }
    }
    __syncthreads();

    int wm = warp * 16;  // warp row base within tile
    float c[8][4];
#pragma unroll
    for (int j = 0; j < 8; j++)
#pragma unroll
        for (int q = 0; q < 4; q++) c[j][q] = 0.f;

#pragma unroll
    for (int ks = 0; ks < 16; ks++) {
        int k = ks * 8;
        // A fragment from smem
        unsigned a0 = f2tf32(Xs[(wm + gid) * XS_STRIDE + k + tig]);
        unsigned a1 = f2tf32(Xs[(wm + gid + 8) * XS_STRIDE + k + tig]);
        unsigned a2 = f2tf32(Xs[(wm + gid) * XS_STRIDE + k + tig + 4]);
        unsigned a3 = f2tf32(Xs[(wm + gid + 8) * XS_STRIDE + k + tig + 4]);
#pragma unroll
        for (int j = 0; j < 8; j++) {
            // B fragment straight from gmem (L1-resident, 32KB total)
            unsigned b0 = f2tf32(__ldg(&W[(k + tig) * 64 + j * 8 + gid]));
            unsigned b1 = f2tf32(__ldg(&W[(k + tig + 4) * 64 + j * 8 + gid]));
            asm volatile(
                "mma.sync.aligned.m16n8k8.row.col.f32.tf32.tf32.f32 "
                "{%0,%1,%2,%3}, {%4,%5,%6,%7}, {%8,%9}, {%0,%1,%2,%3};"
                : "+f"(c[j][0]), "+f"(c[j][1]), "+f"(c[j][2]), "+f"(c[j][3])
                : "r"(a0), "r"(a1), "r"(a2), "r"(a3), "r"(b0), "r"(b1));
        }
    }

    // store: c0,c1 -> (row, 2tig), (row, 2tig+1); c2,c3 -> row+8
    int r0 = rb + wm + gid;
    int r1 = r0 + 8;
#pragma unroll
    for (int j = 0; j < 8; j++) {
        int col = j * 8 + 2 * tig;
        if (r0 < n) *(float2*)&g_h1[(size_t)r0 * DHID + col] = make_float2(c[j][0], c[j][1]);
        if (r1 < n) *(float2*)&g_h1[(size_t)r1 * DHID + col] = make_float2(c[j][2], c[j][3]);
    }
}

// ---------------------------------------------------------------- agg1: warp per dst node, 64 dims (float2/lane)
__global__ __launch_bounds__(256) void k_agg1(int n) {
    int w = (blockIdx.x * 256 + threadIdx.x) >> 5;
    int lane = threadIdx.x & 31;
    if (w >= n) return;
    int beg = g_offs[w];
    int end = beg + g_cnt[w];
    float isqd = g_isq[w];
    const float2* h = (const float2*)g_h1;

    float2 self = h[(size_t)w * 32 + lane];
    float2 acc;
    acc.x = isqd * self.x;
    acc.y = isqd * self.y;

    int j = beg;
    for (; j + 3 < end; j += 4) {
        int s0 = __ldg(&g_csrc[j]),     s1 = __ldg(&g_csrc[j + 1]);
        int s2 = __ldg(&g_csrc[j + 2]), s3 = __ldg(&g_csrc[j + 3]);
        float w0 = __ldg(&g_isq[s0]), w1 = __ldg(&g_isq[s1]);
        float w2 = __ldg(&g_isq[s2]), w3 = __ldg(&g_isq[s3]);
        float2 v0 = h[(size_t)s0 * 32 + lane];
        float2 v1 = h[(size_t)s1 * 32 + lane];
        float2 v2 = h[(size_t)s2 * 32 + lane];
        float2 v3 = h[(size_t)s3 * 32 + lane];
        acc.x = fmaf(w0, v0.x, acc.x); acc.y = fmaf(w0, v0.y, acc.y);
        acc.x = fmaf(w1, v1.x, acc.x); acc.y = fmaf(w1, v1.y, acc.y);
        acc.x = fmaf(w2, v2.x, acc.x); acc.y = fmaf(w2, v2.y, acc.y);
        acc.x = fmaf(w3, v3.x, acc.x); acc.y = fmaf(w3, v3.y, acc.y);
    }
    for (; j < end; j++) {
        int s0 = __ldg(&g_csrc[j]);
        float w0 = __ldg(&g_isq[s0]);
        float2 v0 = h[(size_t)s0 * 32 + lane];
        acc.x = fmaf(w0, v0.x, acc.x);
        acc.y = fmaf(w0, v0.y, acc.y);
    }
    acc.x *= isqd;
    acc.y *= isqd;
    ((float2*)g_a1)[(size_t)w * 32 + lane] = acc;
}

// ---------------------------------------------------------------- GEMM2: h3 = relu(a1+b1) @ W2  [N,64]x[64,32]
__global__ __launch_bounds__(256) void k_gemm2(const float* __restrict__ W,
                                               const float* __restrict__ b1, int n) {
    __shared__ float Xs[64][DHID];  // 16 KB
    int tid = threadIdx.x;
    int rb = blockIdx.x * 64;
    int rows = n - rb; if (rows > 64) rows = 64;

    const float4* a4 = (const float4*)g_a1 + (size_t)rb * (DHID / 4);
    float4* Xs4 = (float4*)Xs;
    const float4* b4 = (const float4*)b1;
    for (int i = tid; i < rows * (DHID / 4); i += 256) {
        float4 v = a4[i];
        float4 b = __ldg(&b4[i & 15]);
        v.x = fmaxf(v.x + b.x, 0.0f);
        v.y = fmaxf(v.y + b.y, 0.0f);
        v.z = fmaxf(v.z + b.z, 0.0f);
        v.w = fmaxf(v.w + b.w, 0.0f);
        Xs4[i] = v;
    }
    __syncthreads();

    int colq = tid & 7;
    int rowq = tid >> 3;
    float acc[2][4] = {};
    const float4* W4 = (const float4*)W;

#pragma unroll 8
    for (int k = 0; k < DHID; k += 4) {
        float4 xr[2];
#pragma unroll
        for (int i = 0; i < 2; i++)
            xr[i] = *(const float4*)&Xs[rowq * 2 + i][k];
#pragma unroll
        for (int kk = 0; kk < 4; kk++) {
            float4 w = __ldg(&W4[(k + kk) * 8 + colq]);
#pragma unroll
            for (int i = 0; i < 2; i++) {
                float xv = ((const float*)&xr[i])[kk];
                acc[i][0] = fmaf(xv, w.x, acc[i][0]);
                acc[i][1] = fmaf(xv, w.y, acc[i][1]);
                acc[i][2] = fmaf(xv, w.z, acc[i][2]);
                acc[i][3] = fmaf(xv, w.w, acc[i][3]);
            }
        }
    }
#pragma unroll
    for (int i = 0; i < 2; i++) {
        int r = rb + rowq * 2 + i;
        if (r < n) {
            float4 v = make_float4(acc[i][0], acc[i][1], acc[i][2], acc[i][3]);
            *(float4*)&g_h3[(size_t)r * DOUT + colq * 4] = v;
        }
    }
}

// ---------------------------------------------------------------- agg2: warp per dst node, 32 dims (float/lane)
__global__ __launch_bounds__(256) void k_agg2(float* __restrict__ out,
                                              const float* __restrict__ b2, int n) {
    int w = (blockIdx.x * 256 + threadIdx.x) >> 5;
    int lane = threadIdx.x & 31;
    if (w >= n) return;
    int beg = g_offs[w];
    int end = beg + g_cnt[w];
    float isqd = g_isq[w];

    float acc = isqd * g_h3[(size_t)w * 32 + lane];

    int j = beg;
    for (; j + 3 < end; j += 4) {
        int s0 = __ldg(&g_csrc[j]),     s1 = __ldg(&g_csrc[j + 1]);
        int s2 = __ldg(&g_csrc[j + 2]), s3 = __ldg(&g_csrc[j + 3]);
        float w0 = __ldg(&g_isq[s0]), w1 = __ldg(&g_isq[s1]);
        float w2 = __ldg(&g_isq[s2]), w3 = __ldg(&g_isq[s3]);
        float v0 = g_h3[(size_t)s0 * 32 + lane];
        float v1 = g_h3[(size_t)s1 * 32 + lane];
        float v2 = g_h3[(size_t)s2 * 32 + lane];
        float v3 = g_h3[(size_t)s3 * 32 + lane];
        acc = fmaf(w0, v0, acc);
        acc = fmaf(w1, v1, acc);
        acc = fmaf(w2, v2, acc);
        acc = fmaf(w3, v3, acc);
    }
    for (; j < end; j++) {
        int s0 = __ldg(&g_csrc[j]);
        acc = fmaf(__ldg(&g_isq[s0]), g_h3[(size_t)s0 * 32 + lane], acc);
    }
    out[(size_t)w * 32 + lane] = fmaf(acc, isqd, __ldg(&b2[lane]));
}

// ----------------------------------------------------------------
extern "C" void kernel_launch(void* const* d_in, const int* in_sizes, int n_in,
                              void* d_out, int out_size) {
    const float* x  = (const float*)d_in[0];
    const int*   ei = (const int*)d_in[1];
    const float* W1 = (const float*)d_in[2];
    const float* b1 = (const float*)d_in[3];
    const float* W2 = (const float*)d_in[4];
    const float* b2 = (const float*)d_in[5];
    float* out = (float*)d_out;

    int n = in_sizes[0] / DIN;
    int e = in_sizes[1] / 2;
    const int* src = ei;
    const int* dst = ei + e;

    // CSR build
    k_zero<<<(n + 255) / 256, 256>>>(n);
    k_count<<<(e + 255) / 256, 256>>>(dst, e);
    k_offsets<<<(n + SCAN_BLK - 1) / SCAN_BLK, SCAN_BLK>>>(n);
    k_fill<<<(e + 255) / 256, 256>>>(src, dst, e);

    // Layer 1
    {
        int smem = 128 * XS_STRIDE * sizeof(float);  // 67584 B
        cudaFuncSetAttribute(k_gemm1_tf32, cudaFuncAttributeMaxDynamicSharedMemorySize, smem);
        k_gemm1_tf32<<<(n + 127) / 128, 256, smem>>>(x, W1, n);
    }
    k_agg1<<<(n * 32 + 255) / 256, 256>>>(n);

    // Layer 2
    k_gemm2<<<(n + 63) / 64, 256>>>(W2, b1, n);
    k_agg2<<<(n * 32 + 255) / 256, 256>>>(out, b2, n);
}

// round 5
// speedup vs baseline: 1.3540x; 1.0002x over previous
#include <cuda_runtime.h>
#include <cuda_bf16.h>

#define NN 100000
#define EE 1600000
#define DIN 128
#define DHID 64
#define DOUT 32
#define SCAN_BLK 1024

// Scratch (allocation-free contract: __device__ globals; zero-init at load,
// and each full run re-zeroes g_cnt/g_etotal in k_agg2's epilogue so graph
// replays see the same initial state)
__device__ int   g_cnt[NN];
__device__ int   g_offs[NN];
__device__ int   g_cursor[NN];
__device__ int   g_etotal;
__device__ float g_isq[NN];        // (deg+1)^{-1/2}
__device__ int   g_csrc[EE];       // CSR-sorted source indices
__device__ float g_h1[NN * DHID];  // x @ W1
__device__ float g_h3[NN * DOUT];  // relu(agg1+b1) @ W2

// ---------------------------------------------------------------- GEMM1 (TF32) + fused edge counting
#define XS_STRIDE 132

__device__ __forceinline__ unsigned f2tf32(float f) {
    unsigned r;
    asm("cvt.rna.tf32.f32 %0, %1;" : "=r"(r) : "f"(f));
    return r;
}

__global__ __launch_bounds__(256) void k_gemm1_count(const float* __restrict__ x,
                                                     const float* __restrict__ W,
                                                     const int* __restrict__ dst,
                                                     int e, int n) {
    extern __shared__ float Xs[];  // [128][XS_STRIDE]
    int tid = threadIdx.x;
    int warp = tid >> 5;
    int lane = tid & 31;
    int gid = lane >> 2;
    int tig = lane & 3;
    int rb = blockIdx.x * 128;

    // stage X tile [128 x 128] as float4, zero-fill OOB rows
    {
        float4* Xs4 = (float4*)Xs;
        const float4 zz = make_float4(0.f, 0.f, 0.f, 0.f);
        for (int idx = tid; idx < 128 * 32; idx += 256) {
            int row = idx >> 5, c4 = idx & 31;
            float4 v = (rb + row < n)
                     ? __ldg((const float4*)(x + (size_t)(rb + row) * DIN) + c4)
                     : zz;
            Xs4[row * (XS_STRIDE / 4) + c4] = v;
        }
    }

    // fire-and-forget degree counting (RED.ADD, no scoreboard wait) — hides under MMA
    {
        int stride = gridDim.x * 256;
        for (int idx = blockIdx.x * 256 + tid; idx < e; idx += stride)
            atomicAdd(&g_cnt[__ldg(&dst[idx])], 1);
    }
    __syncthreads();

    int wm = warp * 16;
    float c[8][4];
#pragma unroll
    for (int j = 0; j < 8; j++)
#pragma unroll
        for (int q = 0; q < 4; q++) c[j][q] = 0.f;

#pragma unroll
    for (int ks = 0; ks < 16; ks++) {
        int k = ks * 8;
        unsigned a0 = f2tf32(Xs[(wm + gid) * XS_STRIDE + k + tig]);
        unsigned a1 = f2tf32(Xs[(wm + gid + 8) * XS_STRIDE + k + tig]);
        unsigned a2 = f2tf32(Xs[(wm + gid) * XS_STRIDE + k + tig + 4]);
        unsigned a3 = f2tf32(Xs[(wm + gid + 8) * XS_STRIDE + k + tig + 4]);
#pragma unroll
        for (int j = 0; j < 8; j++) {
            unsigned b0 = f2tf32(__ldg(&W[(k + tig) * 64 + j * 8 + gid]));
            unsigned b1 = f2tf32(__ldg(&W[(k + tig + 4) * 64 + j * 8 + gid]));
            asm volatile(
                "mma.sync.aligned.m16n8k8.row.col.f32.tf32.tf32.f32 "
                "{%0,%1,%2,%3}, {%4,%5,%6,%7}, {%8,%9}, {%0,%1,%2,%3};"
                : "+f"(c[j][0]), "+f"(c[j][1]), "+f"(c[j][2]), "+f"(c[j][3])
                : "r"(a0), "r"(a1), "r"(a2), "r"(a3), "r"(b0), "r"(b1));
        }
    }

    int r0 = rb + wm + gid;
    int r1 = r0 + 8;
#pragma unroll
    for (int j = 0; j < 8; j++) {
        int col = j * 8 + 2 * tig;
        if (r0 < n) *(float2*)&g_h1[(size_t)r0 * DHID + col] = make_float2(c[j][0], c[j][1]);
        if (r1 < n) *(float2*)&g_h1[(size_t)r1 * DHID + col] = make_float2(c[j][2], c[j][3]);
    }
}

// ---------------------------------------------------------------- offsets: shfl warp-scan, 2 barriers
__global__ __launch_bounds__(SCAN_BLK) void k_offsets(int n) {
    __shared__ int wsum[32];
    __shared__ int base;
    int i = blockIdx.x * SCAN_BLK + threadIdx.x;
    int lane = threadIdx.x & 31;
    int warp = threadIdx.x >> 5;
    int c = (i < n) ? g_cnt[i] : 0;

    // inclusive warp scan
    int v = c;
#pragma unroll
    for (int d = 1; d < 32; d <<= 1) {
        int t = __shfl_up_sync(0xffffffff, v, d);
        if (lane >= d) v += t;
    }
    if (lane == 31) wsum[warp] = v;
    __syncthreads();
    if (warp == 0) {
        int s = wsum[lane];
#pragma unroll
        for (int d = 1; d < 32; d <<= 1) {
            int t = __shfl_up_sync(0xffffffff, s, d);
            if (lane >= d) s += t;
        }
        wsum[lane] = s;
        if (lane == 31) base = atomicAdd(&g_etotal, s);
    }
    __syncthreads();
    int pre = (warp > 0 ? wsum[warp - 1] : 0) + v - c;  // exclusive within block
    if (i < n) {
        int off = base + pre;
        g_offs[i] = off;
        g_cursor[i] = off;
        g_isq[i] = rsqrtf((float)(c + 1));
    }
}

// ---------------------------------------------------------------- fill: 4 edges/thread, int4 loads
__global__ void k_fill(const int* __restrict__ src, const int* __restrict__ dst, int e) {
    int q = e >> 2;  // int4-covered quads
    int i = blockIdx.x * blockDim.x + threadIdx.x;
    if (i < q) {
        int4 s4 = __ldg((const int4*)src + i);
        int4 d4 = __ldg((const int4*)dst + i);
        int p0 = atomicAdd(&g_cursor[d4.x], 1);
        int p1 = atomicAdd(&g_cursor[d4.y], 1);
        int p2 = atomicAdd(&g_cursor[d4.z], 1);
        int p3 = atomicAdd(&g_cursor[d4.w], 1);
        g_csrc[p0] = s4.x;
        g_csrc[p1] = s4.y;
        g_csrc[p2] = s4.z;
        g_csrc[p3] = s4.w;
    } else if (i < q + (e & 3)) {  // tail
        int idx = (q << 2) + (i - q);
        int p = atomicAdd(&g_cursor[dst[idx]], 1);
        g_csrc[p] = src[idx];
    }
}

// ---------------------------------------------------------------- agg1 + relu/bias + GEMM2 fused
// Warp per dst node. Gather-aggregate 64 dims (float2/lane), then row @ W2 via
// smem-broadcast: lane computes output col `lane` (DOUT == 32).
__global__ __launch_bounds__(256) void k_agg1_gemm2(const float* __restrict__ b1,
                                                    const float* __restrict__ W2, int n) {
    __shared__ float row[8][64];
    int w = (blockIdx.x * 256 + threadIdx.x) >> 5;
    int lane = threadIdx.x & 31;
    int ws = threadIdx.x >> 5;
    if (w >= n) return;
    int beg = g_offs[w];
    int end = beg + g_cnt[w];
    float isqd = g_isq[w];
    const float2* h = (const float2*)g_h1;

    float2 self = h[(size_t)w * 32 + lane];
    float2 acc;
    acc.x = isqd * self.x;
    acc.y = isqd * self.y;

    int j = beg;
    for (; j + 3 < end; j += 4) {
        int s0 = __ldg(&g_csrc[j]),     s1 = __ldg(&g_csrc[j + 1]);
        int s2 = __ldg(&g_csrc[j + 2]), s3 = __ldg(&g_csrc[j + 3]);
        float w0 = __ldg(&g_isq[s0]), w1 = __ldg(&g_isq[s1]);
        float w2 = __ldg(&g_isq[s2]), w3 = __ldg(&g_isq[s3]);
        float2 v0 = h[(size_t)s0 * 32 + lane];
        float2 v1 = h[(size_t)s1 * 32 + lane];
        float2 v2 = h[(size_t)s2 * 32 + lane];
        float2 v3 = h[(size_t)s3 * 32 + lane];
        acc.x = fmaf(w0, v0.x, acc.x); acc.y = fmaf(w0, v0.y, acc.y);
        acc.x = fmaf(w1, v1.x, acc.x); acc.y = fmaf(w1, v1.y, acc.y);
        acc.x = fmaf(w2, v2.x, acc.x); acc.y = fmaf(w2, v2.y, acc.y);
        acc.x = fmaf(w3, v3.x, acc.x); acc.y = fmaf(w3, v3.y, acc.y);
    }
    for (; j < end; j++) {
        int s0 = __ldg(&g_csrc[j]);
        float w0 = __ldg(&g_isq[s0]);
        float2 v0 = h[(size_t)s0 * 32 + lane];
        acc.x = fmaf(w0, v0.x, acc.x);
        acc.y = fmaf(w0, v0.y, acc.y);
    }

    // relu(isq*acc + b1) -> smem row
    float2 b = __ldg((const float2*)b1 + lane);
    float r0 = fmaxf(fmaf(acc.x, isqd, b.x), 0.f);
    float r1 = fmaxf(fmaf(acc.y, isqd, b.y), 0.f);
    *(float2*)&row[ws][2 * lane] = make_float2(r0, r1);
    __syncwarp();

    // out col = lane: h3[w][lane] = sum_k row[k] * W2[k*32+lane]
    float o = 0.f;
#pragma unroll 16
    for (int k = 0; k < 64; k++)
        o = fmaf(row[ws][k], __ldg(&W2[k * DOUT + lane]), o);
    g_h3[(size_t)w * DOUT + lane] = o;
}

// ---------------------------------------------------------------- agg2 + state reset epilogue
__global__ __launch_bounds__(256) void k_agg2(float* __restrict__ out,
                                              const float* __restrict__ b2, int n) {
    int w = (blockIdx.x * 256 + threadIdx.x) >> 5;
    int lane = threadIdx.x & 31;
    if (w >= n) return;
    int beg = g_offs[w];
    int cnt = g_cnt[w];
    int end = beg + cnt;
    float isqd = g_isq[w];

    float acc = isqd * g_h3[(size_t)w * 32 + lane];

    int j = beg;
    for (; j + 3 < end; j += 4) {
        int s0 = __ldg(&g_csrc[j]),     s1 = __ldg(&g_csrc[j + 1]);
        int s2 = __ldg(&g_csrc[j + 2]), s3 = __ldg(&g_csrc[j + 3]);
        float w0 = __ldg(&g_isq[s0]), w1 = __ldg(&g_isq[s1]);
        float w2 = __ldg(&g_isq[s2]), w3 = __ldg(&g_isq[s3]);
        float v0 = g_h3[(size_t)s0 * 32 + lane];
        float v1 = g_h3[(size_t)s1 * 32 + lane];
        float v2 = g_h3[(size_t)s2 * 32 + lane];
        float v3 = g_h3[(size_t)s3 * 32 + lane];
        acc = fmaf(w0, v0, acc);
        acc = fmaf(w1, v1, acc);
        acc = fmaf(w2, v2, acc);
        acc = fmaf(w3, v3, acc);
    }
    for (; j < end; j++) {
        int s0 = __ldg(&g_csrc[j]);
        acc = fmaf(__ldg(&g_isq[s0]), g_h3[(size_t)s0 * 32 + lane], acc);
    }
    out[(size_t)w * 32 + lane] = fmaf(acc, isqd, __ldg(&b2[lane]));

    // reset per-run state for next graph replay
    if (lane == 0) g_cnt[w] = 0;
    if (w == 0 && lane == 1) g_etotal = 0;
}

// ----------------------------------------------------------------
extern "C" void kernel_launch(void* const* d_in, const int* in_sizes, int n_in,
                              void* d_out, int out_size) {
    const float* x  = (const float*)d_in[0];
    const int*   ei = (const int*)d_in[1];
    const float* W1 = (const float*)d_in[2];
    const float* b1 = (const float*)d_in[3];
    const float* W2 = (const float*)d_in[4];
    const float* b2 = (const float*)d_in[5];
    float* out = (float*)d_out;

    int n = in_sizes[0] / DIN;
    int e = in_sizes[1] / 2;
    const int* src = ei;
    const int* dst = ei + e;

    // GEMM1 + degree count (fused)
    {
        int smem = 128 * XS_STRIDE * sizeof(float);  // 67584 B
        cudaFuncSetAttribute(k_gemm1_count, cudaFuncAttributeMaxDynamicSharedMemorySize, smem);
        k_gemm1_count<<<(n + 127) / 128, 256, smem>>>(x, W1, dst, e, n);
    }
    k_offsets<<<(n + SCAN_BLK - 1) / SCAN_BLK, SCAN_BLK>>>(n);
    {
        int work = (e >> 2) + (e & 3);
        k_fill<<<(work + 255) / 256, 256>>>(src, dst, e);
    }

    k_agg1_gemm2<<<(n * 32 + 255) / 256, 256>>>(b1, W2, n);
    k_agg2<<<(n * 32 + 255) / 256, 256>>>(out, b2, n);
}

// round 6
// speedup vs baseline: 1.3635x; 1.0070x over previous
#include <cuda_runtime.h>
#include <cuda_fp16.h>

#define NN 100000
#define EE 1600000
#define DIN 128
#define DHID 64
#define DOUT 32
#define SCAN_BLK 1024

// Scratch (allocation-free contract: __device__ globals; zero-init at load,
// g_cnt/g_etotal re-zeroed in k_agg2's epilogue so graph replays see the
// same initial state)
__device__ int     g_cnt[NN];
__device__ int     g_offs[NN];
__device__ int     g_cursor[NN];
__device__ int     g_etotal;
__device__ float   g_isq[NN];              // (deg+1)^{-1/2}
__device__ int     g_csrc[EE];             // CSR-sorted source indices
__device__ float   g_h1[NN * DHID];        // x @ W1 (fp32, gemm1 output)
__device__ __half2 g_h1h[NN * (DHID / 2)]; // isq-scaled h1 in fp16 (128B rows)
__device__ float   g_h3[NN * DOUT];        // isq-scaled layer-2 features

// ---------------------------------------------------------------- GEMM1 (TF32) + fused edge counting
#define XS_STRIDE 132

__device__ __forceinline__ unsigned f2tf32(float f) {
    unsigned r;
    asm("cvt.rna.tf32.f32 %0, %1;" : "=r"(r) : "f"(f));
    return r;
}

__global__ __launch_bounds__(256) void k_gemm1_count(const float* __restrict__ x,
                                                     const float* __restrict__ W,
                                                     const int* __restrict__ dst,
                                                     int e, int n) {
    extern __shared__ float Xs[];  // [128][XS_STRIDE]
    int tid = threadIdx.x;
    int warp = tid >> 5;
    int lane = tid & 31;
    int gid = lane >> 2;
    int tig = lane & 3;
    int rb = blockIdx.x * 128;

    // stage X tile [128 x 128] as float4, zero-fill OOB rows
    {
        float4* Xs4 = (float4*)Xs;
        const float4 zz = make_float4(0.f, 0.f, 0.f, 0.f);
        for (int idx = tid; idx < 128 * 32; idx += 256) {
            int row = idx >> 5, c4 = idx & 31;
            float4 v = (rb + row < n)
                     ? __ldg((const float4*)(x + (size_t)(rb + row) * DIN) + c4)
                     : zz;
            Xs4[row * (XS_STRIDE / 4) + c4] = v;
        }
    }

    // fire-and-forget degree counting (RED.ADD) — hides under MMA
    {
        int stride = gridDim.x * 256;
        for (int idx = blockIdx.x * 256 + tid; idx < e; idx += stride)
            atomicAdd(&g_cnt[__ldg(&dst[idx])], 1);
    }
    __syncthreads();

    int wm = warp * 16;
    float c[8][4];
#pragma unroll
    for (int j = 0; j < 8; j++)
#pragma unroll
        for (int q = 0; q < 4; q++) c[j][q] = 0.f;

#pragma unroll
    for (int ks = 0; ks < 16; ks++) {
        int k = ks * 8;
        unsigned a0 = f2tf32(Xs[(wm + gid) * XS_STRIDE + k + tig]);
        unsigned a1 = f2tf32(Xs[(wm + gid + 8) * XS_STRIDE + k + tig]);
        unsigned a2 = f2tf32(Xs[(wm + gid) * XS_STRIDE + k + tig + 4]);
        unsigned a3 = f2tf32(Xs[(wm + gid + 8) * XS_STRIDE + k + tig + 4]);
#pragma unroll
        for (int j = 0; j < 8; j++) {
            unsigned b0 = f2tf32(__ldg(&W[(k + tig) * 64 + j * 8 + gid]));
            unsigned b1 = f2tf32(__ldg(&W[(k + tig + 4) * 64 + j * 8 + gid]));
            asm volatile(
                "mma.sync.aligned.m16n8k8.row.col.f32.tf32.tf32.f32 "
                "{%0,%1,%2,%3}, {%4,%5,%6,%7}, {%8,%9}, {%0,%1,%2,%3};"
                : "+f"(c[j][0]), "+f"(c[j][1]), "+f"(c[j][2]), "+f"(c[j][3])
                : "r"(a0), "r"(a1), "r"(a2), "r"(a3), "r"(b0), "r"(b1));
        }
    }

    int r0 = rb + wm + gid;
    int r1 = r0 + 8;
#pragma unroll
    for (int j = 0; j < 8; j++) {
        int col = j * 8 + 2 * tig;
        if (r0 < n) *(float2*)&g_h1[(size_t)r0 * DHID + col] = make_float2(c[j][0], c[j][1]);
        if (r1 < n) *(float2*)&g_h1[(size_t)r1 * DHID + col] = make_float2(c[j][2], c[j][3]);
    }
}

// ---------------------------------------------------------------- offsets: shfl warp-scan
__global__ __launch_bounds__(SCAN_BLK) void k_offsets(int n) {
    __shared__ int wsum[32];
    __shared__ int base;
    int i = blockIdx.x * SCAN_BLK + threadIdx.x;
    int lane = threadIdx.x & 31;
    int warp = threadIdx.x >> 5;
    int c = (i < n) ? g_cnt[i] : 0;

    int v = c;
#pragma unroll
    for (int d = 1; d < 32; d <<= 1) {
        int t = __shfl_up_sync(0xffffffff, v, d);
        if (lane >= d) v += t;
    }
    if (lane == 31) wsum[warp] = v;
    __syncthreads();
    if (warp == 0) {
        int s = wsum[lane];
#pragma unroll
        for (int d = 1; d < 32; d <<= 1) {
            int t = __shfl_up_sync(0xffffffff, s, d);
            if (lane >= d) s += t;
        }
        wsum[lane] = s;
        if (lane == 31) base = atomicAdd(&g_etotal, s);
    }
    __syncthreads();
    int pre = (warp > 0 ? wsum[warp - 1] : 0) + v - c;
    if (i < n) {
        int off = base + pre;
        g_offs[i] = off;
        g_cursor[i] = off;
        g_isq[i] = rsqrtf((float)(c + 1));
    }
}

// ---------------------------------------------------------------- fused: CSR fill (8 edges/thread) + h1 scale/convert to fp16
__global__ void k_fill_convert(const int* __restrict__ src, const int* __restrict__ dst,
                               int e, int n, int nfb) {
    if ((int)blockIdx.x < nfb) {
        int q8 = e >> 3;
        int i = blockIdx.x * 256 + threadIdx.x;
        if (i < q8) {
            const int4* s4 = (const int4*)src;
            const int4* d4 = (const int4*)dst;
            int4 sa = __ldg(s4 + 2 * i), sb = __ldg(s4 + 2 * i + 1);
            int4 da = __ldg(d4 + 2 * i), db = __ldg(d4 + 2 * i + 1);
            int p0 = atomicAdd(&g_cursor[da.x], 1);
            int p1 = atomicAdd(&g_cursor[da.y], 1);
            int p2 = atomicAdd(&g_cursor[da.z], 1);
            int p3 = atomicAdd(&g_cursor[da.w], 1);
            int p4 = atomicAdd(&g_cursor[db.x], 1);
            int p5 = atomicAdd(&g_cursor[db.y], 1);
            int p6 = atomicAdd(&g_cursor[db.z], 1);
            int p7 = atomicAdd(&g_cursor[db.w], 1);
            g_csrc[p0] = sa.x; g_csrc[p1] = sa.y;
            g_csrc[p2] = sa.z; g_csrc[p3] = sa.w;
            g_csrc[p4] = sb.x; g_csrc[p5] = sb.y;
            g_csrc[p6] = sb.z; g_csrc[p7] = sb.w;
        } else if (i == q8) {
            for (int idx = q8 << 3; idx < e; idx++) {
                int p = atomicAdd(&g_cursor[dst[idx]], 1);
                g_csrc[p] = src[idx];
            }
        }
    } else {
        // convert: h1h[i] = fp16( isq[row] * h1[i] ), i over n*32 half2 slots
        int i = (blockIdx.x - nfb) * 256 + threadIdx.x;
        if (i < n * 32) {
            float2 v = ((const float2*)g_h1)[i];
            float s = g_isq[i >> 5];
            g_h1h[i] = __floats2half2_rn(v.x * s, v.y * s);
        }
    }
}

// ---------------------------------------------------------------- agg1 + relu/bias + GEMM2 fused
// Warp per dst node; h1' pre-scaled fp16 rows (1 wavefront each).
// Epilogue: W2 transposed in smem [32][68] -> 16 LDS.128 per lane; a1 row
// broadcast via 16 uniform LDS.128. Stores isq-scaled h3'.
__global__ __launch_bounds__(256) void k_agg1_gemm2(const float* __restrict__ b1,
                                                    const float* __restrict__ W2, int n) {
    __shared__ float W2t[32][68];  // padded: conflict-free float4 column reads
    __shared__ float row[8][64];
    int tid = threadIdx.x;
    for (int i = tid; i < DHID * DOUT; i += 256) {
        int k = i >> 5, c = i & 31;
        W2t[c][k] = __ldg(&W2[i]);  // W2[k*32+c]
    }
    __syncthreads();

    int w = (blockIdx.x * 256 + tid) >> 5;
    int lane = tid & 31;
    int ws = tid >> 5;
    if (w >= n) return;
    int beg = g_offs[w];
    int end = beg + g_cnt[w];
    float isqd = g_isq[w];
    const __half2* h = g_h1h;

    float2 acc = __half22float2(h[w * 32 + lane]);  // self term = h1'[w]

    int j = beg;
    for (; j + 3 < end; j += 4) {
        int s0 = __ldg(&g_csrc[j]),     s1 = __ldg(&g_csrc[j + 1]);
        int s2 = __ldg(&g_csrc[j + 2]), s3 = __ldg(&g_csrc[j + 3]);
        float2 f0 = __half22float2(__ldg(&h[s0 * 32 + lane]));
        float2 f1 = __half22float2(__ldg(&h[s1 * 32 + lane]));
        float2 f2 = __half22float2(__ldg(&h[s2 * 32 + lane]));
        float2 f3 = __half22float2(__ldg(&h[s3 * 32 + lane]));
        acc.x += (f0.x + f1.x) + (f2.x + f3.x);
        acc.y += (f0.y + f1.y) + (f2.y + f3.y);
    }
    for (; j < end; j++) {
        int s0 = __ldg(&g_csrc[j]);
        float2 f0 = __half22float2(__ldg(&h[s0 * 32 + lane]));
        acc.x += f0.x;
        acc.y += f0.y;
    }

    // relu(isq*acc + b1) -> smem row
    float2 b = __ldg((const float2*)b1 + lane);
    float r0 = fmaxf(fmaf(acc.x, isqd, b.x), 0.f);
    float r1 = fmaxf(fmaf(acc.y, isqd, b.y), 0.f);
    *(float2*)&row[ws][2 * lane] = make_float2(r0, r1);
    __syncwarp();

    // out col = lane
    float o = 0.f;
    const float4* rf4 = (const float4*)row[ws];
#pragma unroll
    for (int k4 = 0; k4 < 16; k4++) {
        float4 rv = rf4[k4];                              // uniform broadcast
        float4 wv = *(const float4*)&W2t[lane][k4 * 4];   // conflict-free
        o = fmaf(rv.x, wv.x, o);
        o = fmaf(rv.y, wv.y, o);
        o = fmaf(rv.z, wv.z, o);
        o = fmaf(rv.w, wv.w, o);
    }
    g_h3[w * 32 + lane] = isqd * o;  // pre-scaled h3'
}

// ---------------------------------------------------------------- agg2 (+ state reset epilogue)
__global__ __launch_bounds__(256) void k_agg2(float* __restrict__ out,
                                              const float* __restrict__ b2, int n) {
    int w = (blockIdx.x * 256 + threadIdx.x) >> 5;
    int lane = threadIdx.x & 31;
    if (w >= n) return;
    int beg = g_offs[w];
    int end = beg + g_cnt[w];
    float isqd = g_isq[w];

    float acc = g_h3[w * 32 + lane];  // self term = h3'[w]

    int j = beg;
    for (; j + 3 < end; j += 4) {
        int s0 = __ldg(&g_csrc[j]),     s1 = __ldg(&g_csrc[j + 1]);
        int s2 = __ldg(&g_csrc[j + 2]), s3 = __ldg(&g_csrc[j + 3]);
        float v0 = __ldg(&g_h3[s0 * 32 + lane]);
        float v1 = __ldg(&g_h3[s1 * 32 + lane]);
        float v2 = __ldg(&g_h3[s2 * 32 + lane]);
        float v3 = __ldg(&g_h3[s3 * 32 + lane]);
        acc += (v0 + v1) + (v2 + v3);
    }
    for (; j < end; j++) {
        int s0 = __ldg(&g_csrc[j]);
        acc += __ldg(&g_h3[s0 * 32 + lane]);
    }
    out[w * 32 + lane] = fmaf(acc, isqd, __ldg(&b2[lane]));

    // reset per-run state for next graph replay
    if (lane == 0) g_cnt[w] = 0;
    if (w == 0 && lane == 1) g_etotal = 0;
}

// ----------------------------------------------------------------
extern "C" void kernel_launch(void* const* d_in, const int* in_sizes, int n_in,
                              void* d_out, int out_size) {
    const float* x  = (const float*)d_in[0];
    const int*   ei = (const int*)d_in[1];
    const float* W1 = (const float*)d_in[2];
    const float* b1 = (const float*)d_in[3];
    const float* W2 = (const float*)d_in[4];
    const float* b2 = (const float*)d_in[5];
    float* out = (float*)d_out;

    int n = in_sizes[0] / DIN;
    int e = in_sizes[1] / 2;
    const int* src = ei;
    const int* dst = ei + e;

    // GEMM1 + degree count (fused)
    {
        int smem = 128 * XS_STRIDE * sizeof(float);  // 67584 B
        cudaFuncSetAttribute(k_gemm1_count, cudaFuncAttributeMaxDynamicSharedMemorySize, smem);
        k_gemm1_count<<<(n + 127) / 128, 256, smem>>>(x, W1, dst, e, n);
    }
    k_offsets<<<(n + SCAN_BLK - 1) / SCAN_BLK, SCAN_BLK>>>(n);

    // fill (atomic-latency bound) overlapped with h1 scale/convert (streaming)
    {
        int nfb = ((e >> 3) + 1 + 255) / 256;          // fill blocks (incl. tail thread)
        int ncb = (n * 32 + 255) / 256;                // convert blocks
        k_fill_convert<<<nfb + ncb, 256>>>(src, dst, e, n, nfb);
    }

    k_agg1_gemm2<<<(n * 32 + 255) / 256, 256>>>(b1, W2, n);
    k_agg2<<<(n * 32 + 255) / 256, 256>>>(out, b2, n);
}

// round 7
// speedup vs baseline: 1.4112x; 1.0349x over previous
#include <cuda_runtime.h>
#include <cuda_fp16.h>

#define NN 100000
#define EE 1600000
#define DIN 128
#define DHID 64
#define DOUT 32
#define SCAN_BLK 1024
#define AGG_BLOCKS 888

// Scratch (allocation-free contract: __device__ globals; zero-init at load,
// g_cnt/g_etotal re-zeroed in k_agg2 so graph replays see the same state)
__device__ int     g_cnt[NN];
__device__ int     g_offs[NN];
__device__ int     g_cursor[NN];
__device__ int     g_etotal;
__device__ float   g_isq[NN];              // (deg+1)^{-1/2}
__device__ int     g_csrc[EE];             // CSR-sorted source indices
__device__ float   g_h1[NN * DHID];        // x @ W1 (fp32, gemm1 output)
__device__ __half2 g_h1h[NN * (DHID / 2)]; // isq-scaled h1 in fp16 (128B rows)
__device__ float   g_h3[NN * DOUT];        // isq-scaled layer-2 features

// ---------------------------------------------------------------- GEMM1 (TF32) + fused edge counting
#define XS_STRIDE 132

__device__ __forceinline__ unsigned f2tf32(float f) {
    unsigned r;
    asm("cvt.rna.tf32.f32 %0, %1;" : "=r"(r) : "f"(f));
    return r;
}

__global__ __launch_bounds__(256) void k_gemm1_count(const float* __restrict__ x,
                                                     const float* __restrict__ W,
                                                     const int* __restrict__ dst,
                                                     int e, int n) {
    extern __shared__ float Xs[];  // [128][XS_STRIDE]
    int tid = threadIdx.x;
    int warp = tid >> 5;
    int lane = tid & 31;
    int gid = lane >> 2;
    int tig = lane & 3;
    int rb = blockIdx.x * 128;

    {
        float4* Xs4 = (float4*)Xs;
        const float4 zz = make_float4(0.f, 0.f, 0.f, 0.f);
        for (int idx = tid; idx < 128 * 32; idx += 256) {
            int row = idx >> 5, c4 = idx & 31;
            float4 v = (rb + row < n)
                     ? __ldg((const float4*)(x + (size_t)(rb + row) * DIN) + c4)
                     : zz;
            Xs4[row * (XS_STRIDE / 4) + c4] = v;
        }
    }

    // fire-and-forget degree counting (RED.ADD) — hides under MMA
    {
        int stride = gridDim.x * 256;
        for (int idx = blockIdx.x * 256 + tid; idx < e; idx += stride)
            atomicAdd(&g_cnt[__ldg(&dst[idx])], 1);
    }
    __syncthreads();

    int wm = warp * 16;
    float c[8][4];
#pragma unroll
    for (int j = 0; j < 8; j++)
#pragma unroll
        for (int q = 0; q < 4; q++) c[j][q] = 0.f;

#pragma unroll
    for (int ks = 0; ks < 16; ks++) {
        int k = ks * 8;
        unsigned a0 = f2tf32(Xs[(wm + gid) * XS_STRIDE + k + tig]);
        unsigned a1 = f2tf32(Xs[(wm + gid + 8) * XS_STRIDE + k + tig]);
        unsigned a2 = f2tf32(Xs[(wm + gid) * XS_STRIDE + k + tig + 4]);
        unsigned a3 = f2tf32(Xs[(wm + gid + 8) * XS_STRIDE + k + tig + 4]);
#pragma unroll
        for (int j = 0; j < 8; j++) {
            unsigned b0 = f2tf32(__ldg(&W[(k + tig) * 64 + j * 8 + gid]));
            unsigned b1 = f2tf32(__ldg(&W[(k + tig + 4) * 64 + j * 8 + gid]));
            asm volatile(
                "mma.sync.aligned.m16n8k8.row.col.f32.tf32.tf32.f32 "
                "{%0,%1,%2,%3}, {%4,%5,%6,%7}, {%8,%9}, {%0,%1,%2,%3};"
                : "+f"(c[j][0]), "+f"(c[j][1]), "+f"(c[j][2]), "+f"(c[j][3])
                : "r"(a0), "r"(a1), "r"(a2), "r"(a3), "r"(b0), "r"(b1));
        }
    }

    int r0 = rb + wm + gid;
    int r1 = r0 + 8;
#pragma unroll
    for (int j = 0; j < 8; j++) {
        int col = j * 8 + 2 * tig;
        if (r0 < n) *(float2*)&g_h1[(size_t)r0 * DHID + col] = make_float2(c[j][0], c[j][1]);
        if (r1 < n) *(float2*)&g_h1[(size_t)r1 * DHID + col] = make_float2(c[j][2], c[j][3]);
    }
}

// ---------------------------------------------------------------- offsets: shfl warp-scan
__global__ __launch_bounds__(SCAN_BLK) void k_offsets(int n) {
    __shared__ int wsum[32];
    __shared__ int base;
    int i = blockIdx.x * SCAN_BLK + threadIdx.x;
    int lane = threadIdx.x & 31;
    int warp = threadIdx.x >> 5;
    int c = (i < n) ? g_cnt[i] : 0;

    int v = c;
#pragma unroll
    for (int d = 1; d < 32; d <<= 1) {
        int t = __shfl_up_sync(0xffffffff, v, d);
        if (lane >= d) v += t;
    }
    if (lane == 31) wsum[warp] = v;
    __syncthreads();
    if (warp == 0) {
        int s = wsum[lane];
#pragma unroll
        for (int d = 1; d < 32; d <<= 1) {
            int t = __shfl_up_sync(0xffffffff, s, d);
            if (lane >= d) s += t;
        }
        wsum[lane] = s;
        if (lane == 31) base = atomicAdd(&g_etotal, s);
    }
    __syncthreads();
    int pre = (warp > 0 ? wsum[warp - 1] : 0) + v - c;
    if (i < n) {
        int off = base + pre;
        g_offs[i] = off;
        g_cursor[i] = off;
        g_isq[i] = rsqrtf((float)(c + 1));
    }
}

// ---------------------------------------------------------------- fused: CSR fill (8 edges/thread) + h1 scale/convert to fp16
__global__ void k_fill_convert(const int* __restrict__ src, const int* __restrict__ dst,
                               int e, int n, int nfb) {
    if ((int)blockIdx.x < nfb) {
        int q8 = e >> 3;
        int i = blockIdx.x * 256 + threadIdx.x;
        if (i < q8) {
            const int4* s4 = (const int4*)src;
            const int4* d4 = (const int4*)dst;
            int4 sa = __ldg(s4 + 2 * i), sb = __ldg(s4 + 2 * i + 1);
            int4 da = __ldg(d4 + 2 * i), db = __ldg(d4 + 2 * i + 1);
            int p0 = atomicAdd(&g_cursor[da.x], 1);
            int p1 = atomicAdd(&g_cursor[da.y], 1);
            int p2 = atomicAdd(&g_cursor[da.z], 1);
            int p3 = atomicAdd(&g_cursor[da.w], 1);
            int p4 = atomicAdd(&g_cursor[db.x], 1);
            int p5 = atomicAdd(&g_cursor[db.y], 1);
            int p6 = atomicAdd(&g_cursor[db.z], 1);
            int p7 = atomicAdd(&g_cursor[db.w], 1);
            g_csrc[p0] = sa.x; g_csrc[p1] = sa.y;
            g_csrc[p2] = sa.z; g_csrc[p3] = sa.w;
            g_csrc[p4] = sb.x; g_csrc[p5] = sb.y;
            g_csrc[p6] = sb.z; g_csrc[p7] = sb.w;
        } else if (i == q8) {
            for (int idx = q8 << 3; idx < e; idx++) {
                int p = atomicAdd(&g_cursor[dst[idx]], 1);
                g_csrc[p] = src[idx];
            }
        }
    } else {
        int i = (blockIdx.x - nfb) * 256 + threadIdx.x;
        if (i < n * 32) {
            float2 v = ((const float2*)g_h1)[i];
            float s = g_isq[i >> 5];
            g_h1h[i] = __floats2half2_rn(v.x * s, v.y * s);
        }
    }
}

// ---------------------------------------------------------------- agg1 + relu/bias + GEMM2 fused
// Persistent warp-per-node. csrc coalesced per-lane + shfl broadcast;
// 8-deep raw row-load batches; W2 transposed in smem.
__global__ __launch_bounds__(256) void k_agg1_gemm2(const float* __restrict__ b1,
                                                    const float* __restrict__ W2, int n) {
    __shared__ float W2t[32][68];
    __shared__ float row[8][64];
    int tid = threadIdx.x;
    for (int i = tid; i < DHID * DOUT; i += 256) {
        int k = i >> 5, c = i & 31;
        W2t[c][k] = __ldg(&W2[i]);
    }
    __syncthreads();

    int lane = tid & 31;
    int ws = tid >> 5;
    int nwarps = gridDim.x * 8;
    const unsigned* hraw = (const unsigned*)g_h1h;  // row = 32 u32 slots
    float2 b = __ldg((const float2*)b1 + lane);

    for (int w = blockIdx.x * 8 + ws; w < n; w += nwarps) {
        int beg = g_offs[w];
        int deg = g_cnt[w];
        float isqd = g_isq[w];

        float2 acc = __half22float2(g_h1h[w * 32 + lane]);  // self term

        int done = 0;
        while (done < deg) {
            int m = deg - done; if (m > 32) m = 32;
            int sid = (lane < m) ? __ldg(&g_csrc[beg + done + lane]) : 0;
            int j = 0;
            for (; j + 8 <= m; j += 8) {
                unsigned u[8];
#pragma unroll
                for (int t = 0; t < 8; t++) {
                    int s = __shfl_sync(0xffffffff, sid, j + t);
                    u[t] = __ldg(&hraw[s * 32 + lane]);
                }
#pragma unroll
                for (int t = 0; t < 8; t++) {
                    float2 f = __half22float2(*(const __half2*)&u[t]);
                    acc.x += f.x;
                    acc.y += f.y;
                }
            }
            for (; j < m; j++) {
                int s = __shfl_sync(0xffffffff, sid, j);
                float2 f = __half22float2(*(const __half2*)&hraw[s * 32 + lane]);
                acc.x += f.x;
                acc.y += f.y;
            }
            done += m;
        }

        // relu(isq*acc + b1) -> smem row
        float r0 = fmaxf(fmaf(acc.x, isqd, b.x), 0.f);
        float r1 = fmaxf(fmaf(acc.y, isqd, b.y), 0.f);
        *(float2*)&row[ws][2 * lane] = make_float2(r0, r1);
        __syncwarp();

        // out col = lane
        float o = 0.f;
        const float4* rf4 = (const float4*)row[ws];
#pragma unroll
        for (int k4 = 0; k4 < 16; k4++) {
            float4 rv = rf4[k4];
            float4 wv = *(const float4*)&W2t[lane][k4 * 4];
            o = fmaf(rv.x, wv.x, o);
            o = fmaf(rv.y, wv.y, o);
            o = fmaf(rv.z, wv.z, o);
            o = fmaf(rv.w, wv.w, o);
        }
        g_h3[w * 32 + lane] = isqd * o;  // pre-scaled h3'
        __syncwarp();
    }
}

// ---------------------------------------------------------------- agg2: persistent, same gather pattern (+ state reset)
__global__ __launch_bounds__(256) void k_agg2(float* __restrict__ out,
                                              const float* __restrict__ b2, int n) {
    int tid = threadIdx.x;
    int lane = tid & 31;
    int ws = tid >> 5;
    int nwarps = gridDim.x * 8;
    float bb = __ldg(&b2[lane]);
    if (blockIdx.x == 0 && tid == 0) g_etotal = 0;

    for (int w = blockIdx.x * 8 + ws; w < n; w += nwarps) {
        int beg = g_offs[w];
        int deg = g_cnt[w];
        float isqd = g_isq[w];

        float acc = g_h3[w * 32 + lane];  // self term

        int done = 0;
        while (done < deg) {
            int m = deg - done; if (m > 32) m = 32;
            int sid = (lane < m) ? __ldg(&g_csrc[beg + done + lane]) : 0;
            int j = 0;
            for (; j + 8 <= m; j += 8) {
                float v[8];
#pragma unroll
                for (int t = 0; t < 8; t++) {
                    int s = __shfl_sync(0xffffffff, sid, j + t);
                    v[t] = __ldg(&g_h3[s * 32 + lane]);
                }
#pragma unroll
                for (int t = 0; t < 8; t++) acc += v[t];
            }
            for (; j < m; j++) {
                int s = __shfl_sync(0xffffffff, sid, j);
                acc += __ldg(&g_h3[s * 32 + lane]);
            }
            done += m;
        }
        out[w * 32 + lane] = fmaf(acc, isqd, bb);

        if (lane == 0) g_cnt[w] = 0;  // reset for next graph replay
    }
}

// ----------------------------------------------------------------
extern "C" void kernel_launch(void* const* d_in, const int* in_sizes, int n_in,
                              void* d_out, int out_size) {
    const float* x  = (const float*)d_in[0];
    const int*   ei = (const int*)d_in[1];
    const float* W1 = (const float*)d_in[2];
    const float* b1 = (const float*)d_in[3];
    const float* W2 = (const float*)d_in[4];
    const float* b2 = (const float*)d_in[5];
    float* out = (float*)d_out;

    int n = in_sizes[0] / DIN;
    int e = in_sizes[1] / 2;
    const int* src = ei;
    const int* dst = ei + e;

    {
        int smem = 128 * XS_STRIDE * sizeof(float);  // 67584 B
        cudaFuncSetAttribute(k_gemm1_count, cudaFuncAttributeMaxDynamicSharedMemorySize, smem);
        k_gemm1_count<<<(n + 127) / 128, 256, smem>>>(x, W1, dst, e, n);
    }
    k_offsets<<<(n + SCAN_BLK - 1) / SCAN_BLK, SCAN_BLK>>>(n);
    {
        int nfb = ((e >> 3) + 1 + 255) / 256;
        int ncb = (n * 32 + 255) / 256;
        k_fill_convert<<<nfb + ncb, 256>>>(src, dst, e, n, nfb);
    }

    k_agg1_gemm2<<<AGG_BLOCKS, 256>>>(b1, W2, n);
    k_agg2<<<AGG_BLOCKS, 256>>>(out, b2, n);
}